// round 15
// baseline (speedup 1.0000x reference)
#include <cuda_runtime.h>
#include <cstdint>

// ---------------- problem constants ----------------
#define H 128
#define W 128
#define C 256
#define O 256
#define OH 126
#define OW 126

// ---------------- tiling ----------------
#define TH 4              // output rows per CTA tile
#define TW 32             // output cols per CTA tile
#define ROWS (TH + 2)     // input rows needed = 6
#define XT (TW + 2)       // input x-positions = 34
#define XP 34             // x-pitch (>= XT)
#define CH 128            // channels per half
#define RPH (CH * XP)     // row pitch within a half-buffer = 4352 floats

#define BUF_FLOATS (ROWS * CH * XP)     // 26112 floats = 104448 B per buffer
#define CSR_CAP 2560                    // 2048 + 512 buckets even-padding
#define SMEM_BYTES (2 * BUF_FLOATS * 4 + CSR_CAP * 8)   // 208896+20480 = 229376 B
// static s_off[513] = 2052 B -> total 231428 B < 232448 B cap.

__device__ __forceinline__ unsigned smem_u32(const void* p) {
    unsigned a;
    asm("{ .reg .u64 t; cvta.to.shared.u64 t, %1; cvt.u32.u64 %0, t; }"
        : "=r"(a) : "l"(p));
    return a;
}

// ============================================================
// Persistent fused kernel: grid = 4 x 32 = 128 CTAs, 1024 threads.
// CTA owns a [4 x 32] output tile, all 256 o, loops over all batches.
//   phase 0: build 512-bucket CSR (half-major) once, counters overlay bufA
//   pipeline: step s = (batch s>>1, half s&1); stage(s+1) via cp.async
//             into the other buffer while computing step s; direct STG.128
//             output after each batch's second half.
// ============================================================
__global__ void __launch_bounds__(1024, 1)
sparse_conv_kernel(const float* __restrict__ in,
                   const int4* __restrict__ wi4,
                   const float* __restrict__ wv,
                   float* __restrict__ out, int nnz, int B)
{
    extern __shared__ float smem[];
    float* bufA  = smem;                         // 26112 floats
    uint2* s_csr = (uint2*)(smem + 2 * BUF_FLOATS);
    __shared__ int s_off[513];

    const int tid    = threadIdx.x;
    const int warpId = tid >> 5;
    const int lane   = tid & 31;
    const int x0 = blockIdx.x * TW;
    const int y0 = blockIdx.y * TH;

    // ---- phase 0: CSR build; counters overlay bufA ----
    int* cnt = (int*)bufA;            // 512 ints
    int* cur = cnt + 512;             // 512 ints
    cnt[tid] = 0;                     // tid 0..1023 covers cnt+cur exactly
    // fetch my COO entries
    int4  w0 = make_int4(0, 0, 0, 0), w1 = w0;
    float v0 = 0.0f, v1 = 0.0f;
    const bool e0 = (tid < nnz);
    const bool e1 = (tid + 1024 < nnz);
    if (e0) { w0 = wi4[tid];        v0 = wv[tid]; }
    if (e1) { w1 = wi4[tid + 1024]; v1 = wv[tid + 1024]; }
    __syncthreads();

    // decode (reference (kh,kw,C)-vs-(C,kh,kw) flatten-mismatch remap) + count
    int b0 = 0, o0 = 0, b1 = 0, o1 = 0;
    if (e0) {
        int k  = w0.y * (3 * C) + w0.z * C + w0.w;
        int ce = k / 9; int t = k - 9 * ce; int dy = t / 3; int dx = t - 3 * dy;
        b0 = ((ce >> 7) << 8) | w0.x;                 // bucket = half*256 + o
        o0 = (dy * CH + (ce & 127)) * XP + dx;        // offset in half-buffer
        atomicAdd(&cnt[b0], 1);
    }
    if (e1) {
        int k  = w1.y * (3 * C) + w1.z * C + w1.w;
        int ce = k / 9; int t = k - 9 * ce; int dy = t / 3; int dx = t - 3 * dy;
        b1 = ((ce >> 7) << 8) | w1.x;
        o1 = (dy * CH + (ce & 127)) * XP + dx;
        atomicAdd(&cnt[b1], 1);
    }
    __syncthreads();

    // exclusive scan of 512 even-padded counts (warp 0, 16/lane)
    if (tid < 32) {
        int base = tid * 16;
        int loc[16], run = 0;
#pragma unroll
        for (int j = 0; j < 16; j++) {
            int c = (cnt[base + j] + 1) & ~1;
            loc[j] = run; run += c;
        }
        int incl = run;
#pragma unroll
        for (int d = 1; d < 32; d <<= 1) {
            int n = __shfl_up_sync(0xffffffffu, incl, d);
            if (tid >= d) incl += n;
        }
        int excl = incl - run;
#pragma unroll
        for (int j = 0; j < 16; j++) s_off[base + j] = excl + loc[j];
        if (tid == 31) s_off[512] = incl;
    }
    __syncthreads();

    // scatter
    if (e0) {
        int p = s_off[b0] + atomicAdd(&cur[b0], 1);
        s_csr[p] = make_uint2((unsigned)o0, __float_as_uint(v0));
    }
    if (e1) {
        int p = s_off[b1] + atomicAdd(&cur[b1], 1);
        s_csr[p] = make_uint2((unsigned)o1, __float_as_uint(v1));
    }
    __syncthreads();
    if (tid < 512) {                   // zero pad slots (reads cnt before wipe)
        int c = cnt[tid];
        if (c & 1) s_csr[s_off[tid] + c] = make_uint2(0u, 0u);
    }
    __syncthreads();

    // zero both buffers (counters dead; OOB halo cells must read as 0)
    for (int i = tid; i < 2 * BUF_FLOATS; i += 1024) smem[i] = 0.0f;
    __syncthreads();

    // ---- pipeline ----
    const unsigned sbase = smem_u32(smem);
    const int steps = 2 * B;

    // stage step s into buffer (s&1) via cp.async (4B), 4 channel-groups
    auto stage = [&](int s) {
        const int bz = s >> 1, h = s & 1;
        const unsigned bb = sbase + (unsigned)(h * BUF_FLOATS * 4);
#pragma unroll
        for (int t = 0; t < 7; t++) {
            int p = warpId + (t << 5);
            if (p < ROWS * XT) {
                int rr = p / XT, xx = p - rr * XT;
                int iy = y0 + rr, ix = x0 + xx;
                if ((iy < H) && (ix < W)) {
                    const float* g = in + (((bz * H + iy) * W + ix) * C) + h * CH + lane;
                    unsigned d = bb + (unsigned)((((rr * CH + lane) * XP) + xx) << 2);
#pragma unroll
                    for (int cg = 0; cg < 4; cg++)
                        asm volatile("cp.async.ca.shared.global [%0], [%1], 4;"
                                     :: "r"(d + cg * (32 * XP * 4)), "l"(g + cg * 32)
                                     : "memory");
                }
            }
        }
    };

    const int oBase = warpId * 8;
    float acc[8][TH];
#pragma unroll
    for (int oo = 0; oo < 8; oo++)
#pragma unroll
        for (int r = 0; r < TH; r++) acc[oo][r] = 0.0f;

    // prologue: stage step 0
    stage(0);
    asm volatile("cp.async.wait_all;" ::: "memory");
    __syncthreads();

    for (int s = 0; s < steps; s++) {
        const int h = s & 1;
        if (s + 1 < steps) stage(s + 1);          // async, other buffer

        // compute on buffer h with csr half h
        const float* cbl = smem + h * BUF_FLOATS + lane;
#pragma unroll
        for (int oo = 0; oo < 8; oo++) {
            const int b  = (h << 8) + oBase + oo;
            const int k0 = s_off[b];
            const int k1 = s_off[b + 1];
#pragma unroll 2
            for (int k = k0; k < k1; k += 2) {
                uint4 e = *(const uint4*)(s_csr + k);   // 2 entries, 16B aligned
                const float* a0 = cbl + e.x;
                const float* a1 = cbl + e.z;
                float d0[TH], d1[TH];
#pragma unroll
                for (int r = 0; r < TH; r++) d0[r] = a0[r * RPH];
#pragma unroll
                for (int r = 0; r < TH; r++) d1[r] = a1[r * RPH];
                const float f0 = __uint_as_float(e.y);
                const float f1 = __uint_as_float(e.w);
#pragma unroll
                for (int r = 0; r < TH; r++) acc[oo][r] = fmaf(f0, d0[r], acc[oo][r]);
#pragma unroll
                for (int r = 0; r < TH; r++) acc[oo][r] = fmaf(f1, d1[r], acc[oo][r]);
            }
        }

        if (h) {   // end of batch: direct coalesced-by-sector STG.128, reset acc
            const int bz = s >> 1;
            const int gx = x0 + lane;
#pragma unroll
            for (int r = 0; r < TH; r++) {
                int gy = y0 + r;
                if (gy < OH && gx < OW) {
                    float4* p = (float4*)(out + (((size_t)bz * OH + gy) * OW + gx) * O + oBase);
                    p[0] = make_float4(acc[0][r], acc[1][r], acc[2][r], acc[3][r]);
                    p[1] = make_float4(acc[4][r], acc[5][r], acc[6][r], acc[7][r]);
                }
            }
#pragma unroll
            for (int oo = 0; oo < 8; oo++)
#pragma unroll
                for (int r = 0; r < TH; r++) acc[oo][r] = 0.0f;
        }

        asm volatile("cp.async.wait_all;" ::: "memory");  // next buffer staged
        __syncthreads();                                   // + all reads done
    }
}

// ============================================================
extern "C" void kernel_launch(void* const* d_in, const int* in_sizes, int n_in,
                              void* d_out, int out_size)
{
    const float* in  = (const float*)d_in[0];
    const int4*  wi4 = (const int4*)d_in[1];   // int32 indices, 4 per entry
    const float* wv  = (const float*)d_in[2];
    float*       out = (float*)d_out;

    int nnz = in_sizes[2];
    if (nnz > 2048) nnz = 2048;
    int B = in_sizes[0] / (H * W * C);

    cudaFuncSetAttribute(sparse_conv_kernel,
                         cudaFuncAttributeMaxDynamicSharedMemorySize, SMEM_BYTES);

    dim3 grid((OW + TW - 1) / TW, (OH + TH - 1) / TH, 1);   // 4 x 32 = 128 CTAs
    sparse_conv_kernel<<<grid, 1024, SMEM_BYTES>>>(in, wi4, wv, out, nnz, B);
}

// round 16
// speedup vs baseline: 1.1639x; 1.1639x over previous
#include <cuda_runtime.h>
#include <cstdint>

// ---------------- problem constants ----------------
#define H 128
#define W 128
#define C 256
#define O 256
#define KH 3
#define KW 3
#define OH 126
#define OW 126

#define NNZ_PAD 2304          // 2048 + 256 (buckets padded to EVEN length)

// ---------------- tiling ----------------
#define TH 4            // output rows per block
#define TW 32           // output cols per block
#define ROWS (TH + 2)   // input rows needed = 6
#define XT (TW + 2)     // input x-positions needed = 34
#define XP 34           // x-pitch (MUST be >= XT)
#define RPITCH (C * XP) // row pitch in s_in (floats) = 8704

#define S_IN_FLOATS (ROWS * C * XP)                  // 52224 floats = 208896 B
#define SMEM_BYTES  (S_IN_FLOATS * 4 + NNZ_PAD * 8)  // 227328 B dynamic
// static: s_off 1028 + s_cnt 1024 + s_cur 1024 = 3076
// total 230404 B < 232448 B cap.

// ============================================================
// Persistent fused kernel: grid = 4x32 = 128 CTAs (single wave),
// 1024 threads. CTA = [4 x 32] tile, all 256 o, loops all batches.
//   phase 0: in-CTA CSR build from raw COO (once)
//   per batch: stage input -> gather-accumulate -> DIRECT STG.128
// ============================================================
__global__ void __launch_bounds__(1024, 1)
sparse_conv_kernel(const float* __restrict__ in,
                   const int4* __restrict__ wi4,
                   const float* __restrict__ wv,
                   float* __restrict__ out, int nnz, int B)
{
    extern __shared__ float smem[];
    float* s_in  = smem;                              // 52224 floats
    uint2* s_csr = (uint2*)(smem + S_IN_FLOATS);      // 2304 entries
    __shared__ int s_off[O + 1];
    __shared__ int s_cnt[O];
    __shared__ int s_cur[O];

    const int tid    = threadIdx.x;
    const int warpId = tid >> 5;
    const int lane   = tid & 31;

    const int x0 = blockIdx.x * TW;
    const int y0 = blockIdx.y * TH;

    // ---- phase 0: build CSR in smem (ONCE per CTA) ----
    if (tid < O) { s_cnt[tid] = 0; s_cur[tid] = 0; }

    int4  w0 = make_int4(0, 0, 0, 0), w1 = w0;
    float v0 = 0.0f, v1 = 0.0f;
    const bool h0 = (tid < nnz);
    const bool h1 = (tid + 1024 < nnz);
    if (h0) { w0 = wi4[tid];        v0 = wv[tid]; }
    if (h1) { w1 = wi4[tid + 1024]; v1 = wv[tid + 1024]; }
    __syncthreads();                       // zeroing visible

    if (h0) atomicAdd(&s_cnt[w0.x], 1);
    if (h1) atomicAdd(&s_cnt[w1.x], 1);
    __syncthreads();                       // counts complete

    // exclusive scan of 256 even-padded counts (warp 0)
    if (tid < 32) {
        int base = tid * 8;
        int loc[8], run = 0;
#pragma unroll
        for (int j = 0; j < 8; j++) {
            int c = (s_cnt[base + j] + 1) & ~1;   // pad to even
            loc[j] = run; run += c;
        }
        int incl = run;
#pragma unroll
        for (int d = 1; d < 32; d <<= 1) {
            int n = __shfl_up_sync(0xffffffffu, incl, d);
            if (tid >= d) incl += n;
        }
        int excl = incl - run;
#pragma unroll
        for (int j = 0; j < 8; j++) s_off[base + j] = excl + loc[j];
        if (tid == 31) s_off[O] = incl;
    }
    __syncthreads();                       // s_off ready

    // scatter entries (with reference flatten-mismatch remap)
    if (h0) {
        int k  = w0.y * (KW * C) + w0.z * C + w0.w;  // flat idx in W.reshape(O,-1)
        int ce = k / 9;
        int t  = k - 9 * ce;
        int dy = t / 3;
        int dx = t - 3 * dy;
        int off = (dy * C + ce) * XP + dx;
        int pos = s_off[w0.x] + atomicAdd(&s_cur[w0.x], 1);
        s_csr[pos] = make_uint2((unsigned)off, __float_as_uint(v0));
    }
    if (h1) {
        int k  = w1.y * (KW * C) + w1.z * C + w1.w;
        int ce = k / 9;
        int t  = k - 9 * ce;
        int dy = t / 3;
        int dx = t - 3 * dy;
        int off = (dy * C + ce) * XP + dx;
        int pos = s_off[w1.x] + atomicAdd(&s_cur[w1.x], 1);
        s_csr[pos] = make_uint2((unsigned)off, __float_as_uint(v1));
    }
    if (tid < O) {                          // zero the pad slot per bucket
        int c = s_cnt[tid];
        if (c & 1) s_csr[s_off[tid] + c] = make_uint2(0u, 0u);
    }
    // (sync at top of batch loop covers CSR visibility)

    const int oBase = warpId * 8;
    const float* s_in_lane = s_in + lane;
    const int gx = x0 + lane;

    // ================= persistent batch loop =================
    for (int bz = 0; bz < B; bz++) {

        // ---- stage input tile [row][c][x], one pixel/warp-iter ----
        // ROWS*XT = 204 pixels, 32 warps -> 7 iterations (last partial)
#pragma unroll
        for (int t = 0; t < 7; t++) {
            int p = warpId + (t << 5);
            if (p < ROWS * XT) {
                int rr = p / XT;
                int xx = p - rr * XT;
                int iy = y0 + rr;
                int ix = x0 + xx;
                float* sb = s_in + (rr * C + lane) * XP + xx;
                if ((iy < H) && (ix < W)) {
                    const float* gb = in + (((bz * H + iy) * W + ix) * C) + lane;
                    float v[8];
#pragma unroll
                    for (int cg = 0; cg < 8; cg++) v[cg] = gb[cg * 32];
#pragma unroll
                    for (int cg = 0; cg < 8; cg++) sb[cg * 32 * XP] = v[cg];
                } else {
#pragma unroll
                    for (int cg = 0; cg < 8; cg++) sb[cg * 32 * XP] = 0.0f;
                }
            }
        }
        __syncthreads();     // CSR (first iter) + staged tile ready

        // ---- gather-accumulate: 8 o per warp, lane = x ----
        float acc[8][TH];
#pragma unroll
        for (int oo = 0; oo < 8; oo++)
#pragma unroll
            for (int r = 0; r < TH; r++) acc[oo][r] = 0.0f;

#pragma unroll
        for (int oo = 0; oo < 8; oo++) {
            const int k0 = s_off[oBase + oo];
            const int k1 = s_off[oBase + oo + 1];
#pragma unroll 2
            for (int k = k0; k < k1; k += 2) {
                uint4 e = *(const uint4*)(s_csr + k);    // 2 entries, 16B aligned
                const float* a0 = s_in_lane + e.x;
                const float* a1 = s_in_lane + e.z;
                float d0[TH], d1[TH];
#pragma unroll
                for (int r = 0; r < TH; r++) d0[r] = a0[r * RPITCH];
#pragma unroll
                for (int r = 0; r < TH; r++) d1[r] = a1[r * RPITCH];
                const float f0 = __uint_as_float(e.y);
                const float f1 = __uint_as_float(e.w);
#pragma unroll
                for (int r = 0; r < TH; r++) acc[oo][r] = fmaf(f0, d0[r], acc[oo][r]);
#pragma unroll
                for (int r = 0; r < TH; r++) acc[oo][r] = fmaf(f1, d1[r], acc[oo][r]);
            }
        }

        // ---- direct store: warp w owns o [8w, 8w+8) for all tile pixels ----
        // lane = x; two STG.128 per row; 4 warps fill each 128B line as
        // 4 x 32B sectors (merged in L2). No smem, no extra syncs.
        if (gx < OW) {
#pragma unroll
            for (int r = 0; r < TH; r++) {
                int gy = y0 + r;
                if (gy < OH) {
                    float4* p = (float4*)(out +
                        (((size_t)bz * OH + gy) * OW + gx) * O + oBase);
                    p[0] = make_float4(acc[0][r], acc[1][r], acc[2][r], acc[3][r]);
                    p[1] = make_float4(acc[4][r], acc[5][r], acc[6][r], acc[7][r]);
                }
            }
        }
        __syncthreads();   // all reads of s_in done before next batch staging
    }
}

// ============================================================
extern "C" void kernel_launch(void* const* d_in, const int* in_sizes, int n_in,
                              void* d_out, int out_size)
{
    const float* in  = (const float*)d_in[0];
    const int4*  wi4 = (const int4*)d_in[1];   // int32 indices, 4 per entry
    const float* wv  = (const float*)d_in[2];
    float*       out = (float*)d_out;

    int nnz = in_sizes[2];
    if (nnz > 2048) nnz = 2048;
    int B = in_sizes[0] / (H * W * C);

    cudaFuncSetAttribute(sparse_conv_kernel,
                         cudaFuncAttributeMaxDynamicSharedMemorySize, SMEM_BYTES);

    dim3 grid((OW + TW - 1) / TW, (OH + TH - 1) / TH, 1);   // 4 x 32 = 128 CTAs
    sparse_conv_kernel<<<grid, 1024, SMEM_BYTES>>>(in, wi4, wv, out, nnz, B);
}

// round 17
// speedup vs baseline: 1.3498x; 1.1597x over previous
#include <cuda_runtime.h>
#include <cstdint>

// ---------------- problem constants ----------------
#define H 128
#define W 128
#define C 256
#define O 256
#define KH 3
#define KW 3
#define OH 126
#define OW 126

#define NNZ_PAD 2304          // 2048 + 256 (buckets padded to EVEN length)

// ---------------- tiling ----------------
#define TH 4            // output rows per block
#define TW 32           // output cols per block
#define ROWS (TH + 2)   // input rows needed = 6
#define XT (TW + 2)     // input x-positions needed = 34
#define XP 34           // x-pitch (MUST be >= XT)
#define RPITCH (C * XP) // row pitch in s_in (floats) = 8704

#define S_IN_FLOATS (ROWS * C * XP)                  // 52224 floats = 208896 B
#define SMEM_BYTES  (S_IN_FLOATS * 4 + NNZ_PAD * 8)  // 227328 B dynamic
// static: s_off 1028 + s_cnt 1024 + s_cur 1024 = 3076
// total 230404 B < 232448 B cap.

// ============================================================
// Persistent fused kernel: grid = 4x32 = 128 CTAs (single wave),
// 1024 threads. CTA = [4 x 32] tile, all 256 o, loops all batches.
//   phase 0: in-CTA CSR build from raw COO (once)
//   per batch: stage input -> gather-accumulate ->
//              swizzled vector transpose-store (STS/LDS/STG all .128)
// ============================================================
__global__ void __launch_bounds__(1024, 1)
sparse_conv_kernel(const float* __restrict__ in,
                   const int4* __restrict__ wi4,
                   const float* __restrict__ wv,
                   float* __restrict__ out, int nnz, int B)
{
    extern __shared__ float smem[];
    float* s_in  = smem;                              // 52224 floats
    uint2* s_csr = (uint2*)(smem + S_IN_FLOATS);      // 2304 entries
    __shared__ int s_off[O + 1];
    __shared__ int s_cnt[O];
    __shared__ int s_cur[O];

    const int tid    = threadIdx.x;
    const int warpId = tid >> 5;
    const int lane   = tid & 31;

    const int x0 = blockIdx.x * TW;
    const int y0 = blockIdx.y * TH;

    // ---- phase 0: build CSR in smem (ONCE per CTA) ----
    if (tid < O) { s_cnt[tid] = 0; s_cur[tid] = 0; }

    int4  w0 = make_int4(0, 0, 0, 0), w1 = w0;
    float v0 = 0.0f, v1 = 0.0f;
    const bool h0 = (tid < nnz);
    const bool h1 = (tid + 1024 < nnz);
    if (h0) { w0 = wi4[tid];        v0 = wv[tid]; }
    if (h1) { w1 = wi4[tid + 1024]; v1 = wv[tid + 1024]; }
    __syncthreads();                       // zeroing visible

    if (h0) atomicAdd(&s_cnt[w0.x], 1);
    if (h1) atomicAdd(&s_cnt[w1.x], 1);
    __syncthreads();                       // counts complete

    // exclusive scan of 256 even-padded counts (warp 0)
    if (tid < 32) {
        int base = tid * 8;
        int loc[8], run = 0;
#pragma unroll
        for (int j = 0; j < 8; j++) {
            int c = (s_cnt[base + j] + 1) & ~1;   // pad to even
            loc[j] = run; run += c;
        }
        int incl = run;
#pragma unroll
        for (int d = 1; d < 32; d <<= 1) {
            int n = __shfl_up_sync(0xffffffffu, incl, d);
            if (tid >= d) incl += n;
        }
        int excl = incl - run;
#pragma unroll
        for (int j = 0; j < 8; j++) s_off[base + j] = excl + loc[j];
        if (tid == 31) s_off[O] = incl;
    }
    __syncthreads();                       // s_off ready

    // scatter entries (with reference flatten-mismatch remap)
    if (h0) {
        int k  = w0.y * (KW * C) + w0.z * C + w0.w;  // flat idx in W.reshape(O,-1)
        int ce = k / 9;
        int t  = k - 9 * ce;
        int dy = t / 3;
        int dx = t - 3 * dy;
        int off = (dy * C + ce) * XP + dx;
        int pos = s_off[w0.x] + atomicAdd(&s_cur[w0.x], 1);
        s_csr[pos] = make_uint2((unsigned)off, __float_as_uint(v0));
    }
    if (h1) {
        int k  = w1.y * (KW * C) + w1.z * C + w1.w;
        int ce = k / 9;
        int t  = k - 9 * ce;
        int dy = t / 3;
        int dx = t - 3 * dy;
        int off = (dy * C + ce) * XP + dx;
        int pos = s_off[w1.x] + atomicAdd(&s_cur[w1.x], 1);
        s_csr[pos] = make_uint2((unsigned)off, __float_as_uint(v1));
    }
    if (tid < O) {                          // zero the pad slot per bucket
        int c = s_cnt[tid];
        if (c & 1) s_csr[s_off[tid] + c] = make_uint2(0u, 0u);
    }
    // (sync at top of batch loop covers CSR visibility)

    const int oBase = warpId * 8;
    const float* s_in_lane = s_in + lane;

    // ================= persistent batch loop =================
    for (int bz = 0; bz < B; bz++) {

        // ---- stage input tile [row][c][x], one pixel/warp-iter ----
        // ROWS*XT = 204 pixels, 32 warps -> 7 iterations (last partial)
#pragma unroll
        for (int t = 0; t < 7; t++) {
            int p = warpId + (t << 5);
            if (p < ROWS * XT) {
                int rr = p / XT;
                int xx = p - rr * XT;
                int iy = y0 + rr;
                int ix = x0 + xx;
                float* sb = s_in + (rr * C + lane) * XP + xx;
                if ((iy < H) && (ix < W)) {
                    const float* gb = in + (((bz * H + iy) * W + ix) * C) + lane;
                    float v[8];
#pragma unroll
                    for (int cg = 0; cg < 8; cg++) v[cg] = gb[cg * 32];
#pragma unroll
                    for (int cg = 0; cg < 8; cg++) sb[cg * 32 * XP] = v[cg];
                } else {
#pragma unroll
                    for (int cg = 0; cg < 8; cg++) sb[cg * 32 * XP] = 0.0f;
                }
            }
        }
        __syncthreads();     // CSR (first iter) + staged tile ready

        // ---- gather-accumulate: 8 o per warp, lane = x ----
        float acc[8][TH];
#pragma unroll
        for (int oo = 0; oo < 8; oo++)
#pragma unroll
            for (int r = 0; r < TH; r++) acc[oo][r] = 0.0f;

#pragma unroll
        for (int oo = 0; oo < 8; oo++) {
            const int k0 = s_off[oBase + oo];
            const int k1 = s_off[oBase + oo + 1];
#pragma unroll 2
            for (int k = k0; k < k1; k += 2) {
                uint4 e = *(const uint4*)(s_csr + k);    // 2 entries, 16B aligned
                const float* a0 = s_in_lane + e.x;
                const float* a1 = s_in_lane + e.z;
                float d0[TH], d1[TH];
#pragma unroll
                for (int r = 0; r < TH; r++) d0[r] = a0[r * RPITCH];
#pragma unroll
                for (int r = 0; r < TH; r++) d1[r] = a1[r * RPITCH];
                const float f0 = __uint_as_float(e.y);
                const float f1 = __uint_as_float(e.w);
#pragma unroll
                for (int r = 0; r < TH; r++) acc[oo][r] = fmaf(f0, d0[r], acc[oo][r]);
#pragma unroll
                for (int r = 0; r < TH; r++) acc[oo][r] = fmaf(f1, d1[r], acc[oo][r]);
            }
        }
        __syncthreads();   // s_in reads done -> reuse as s_out

        // ---- swizzled vector transpose-store ----
        // s_out layout: [pixel p = r*TW+x][o], pitch 256 words (no pad);
        // o-quad m (4 floats) stored at quad index q = m ^ (p & 7):
        // both STS.128 and LDS.128 hit 8 distinct 16B quads per 8-lane
        // phase -> conflict-free. 32768 floats <= 52224 available.
        float* s_out = s_in;
        {
            const int m0 = 2 * warpId;                 // my first o-quad
#pragma unroll
            for (int r = 0; r < TH; r++) {
                int row = r * TW + lane;               // pixel index
                int s   = row & 7;
                float* base = s_out + row * 256;
                *(float4*)(base + 4 * (m0 ^ s)) =
                    make_float4(acc[0][r], acc[1][r], acc[2][r], acc[3][r]);
                *(float4*)(base + 4 * ((m0 + 1) ^ s)) =
                    make_float4(acc[4][r], acc[5][r], acc[6][r], acc[7][r]);
            }
        }
        __syncthreads();

        // each iteration: warp owns one (pixel, o-half); lane = o-quad
        // LDS.128 conflict-free (quad XOR), STG.128 -> 512B contiguous/warp
#pragma unroll
        for (int i = 0; i < 8; i++) {
            int p  = warpId + ((i >> 1) << 5);         // pixel 0..127
            int hh = i & 1;                            // o-half
            int r  = p >> 5;
            int xx = p & 31;
            int gy = y0 + r;
            int gx = x0 + xx;
            if (gy < OH && gx < OW) {
                int m = lane + (hh << 5);              // o-quad 0..63
                int q = m ^ (p & 7);
                float4 v = *(const float4*)(s_out + p * 256 + 4 * q);
                *(float4*)(out + (((size_t)bz * OH + gy) * OW + gx) * O + 4 * m) = v;
            }
        }
        __syncthreads();   // s_out dead before next batch's staging
    }
}

// ============================================================
extern "C" void kernel_launch(void* const* d_in, const int* in_sizes, int n_in,
                              void* d_out, int out_size)
{
    const float* in  = (const float*)d_in[0];
    const int4*  wi4 = (const int4*)d_in[1];   // int32 indices, 4 per entry
    const float* wv  = (const float*)d_in[2];
    float*       out = (float*)d_out;

    int nnz = in_sizes[2];
    if (nnz > 2048) nnz = 2048;
    int B = in_sizes[0] / (H * W * C);

    cudaFuncSetAttribute(sparse_conv_kernel,
                         cudaFuncAttributeMaxDynamicSharedMemorySize, SMEM_BYTES);

    dim3 grid((OW + TW - 1) / TW, (OH + TH - 1) / TH, 1);   // 4 x 32 = 128 CTAs
    sparse_conv_kernel<<<grid, 1024, SMEM_BYTES>>>(in, wi4, wv, out, nnz, B);
}